// round 1
// baseline (speedup 1.0000x reference)
#include <cuda_runtime.h>

#define BB 8
#define NN 2000
#define CC 81
#define NPAD 2048
#define MAXI 100
#define HH 512
#define WW 512

// scratch (device globals: no allocation allowed)
__device__ float g_box[BB * NN * 4];
__device__ int g_cls[BB * NN];
__device__ unsigned long long g_key[BB * NPAD];

// ---------------------------------------------------------------------------
// K1: per-proposal argmax class, score, refined+clipped box, sort key
// ---------------------------------------------------------------------------
__global__ void k1_refine(const float* __restrict__ rois,
                          const float* __restrict__ probs,
                          const float* __restrict__ deltas,
                          const float* __restrict__ stdv) {
    int t = blockIdx.x * blockDim.x + threadIdx.x;
    if (t >= BB * NN) return;

    const float* p = probs + (long long)t * CC;
    float best = p[0];
    int bc = 0;
#pragma unroll 1
    for (int c = 1; c < CC; ++c) {
        float v = p[c];
        if (v > best) { best = v; bc = c; }  // strict > == first max (jnp.argmax)
    }

    const float* dd = deltas + ((long long)t * CC + bc) * 4;
    float dy = dd[0] * stdv[0];
    float dx = dd[1] * stdv[1];
    float dh = dd[2] * stdv[2];
    float dw = dd[3] * stdv[3];

    const float* r = rois + t * 4;
    float y1 = r[0], x1 = r[1], y2 = r[2], x2 = r[3];
    float h = y2 - y1, w = x2 - x1;
    float cy = y1 + 0.5f * h + dy * h;
    float cx = x1 + 0.5f * w + dx * w;
    h = h * expf(dh);
    w = w * expf(dw);
    float ny1 = fminf(fmaxf(cy - 0.5f * h, 0.0f), 1.0f);
    float nx1 = fminf(fmaxf(cx - 0.5f * w, 0.0f), 1.0f);
    float ny2 = fminf(fmaxf(cy + 0.5f * h, 0.0f), 1.0f);
    float nx2 = fminf(fmaxf(cx + 0.5f * w, 0.0f), 1.0f);

    g_box[t * 4 + 0] = ny1;
    g_box[t * 4 + 1] = nx1;
    g_box[t * 4 + 2] = ny2;
    g_box[t * 4 + 3] = nx2;
    g_cls[t] = bc;

    int b = t / NN;
    int n = t - b * NN;
    bool valid = (bc > 0) && (best >= 0.05f);
    // score in (0,1] -> float bits are monotone uint; tie-break: smaller index
    // sorts first under DESCENDING sort via (0xFFFFFFFF - n).
    unsigned long long key =
        valid ? ((((unsigned long long)__float_as_uint(best)) << 32) |
                 (unsigned long long)(0xFFFFFFFFu - (unsigned)n))
              : 0ull;
    g_key[b * NPAD + n] = key;
}

// ---------------------------------------------------------------------------
// K2: per-batch bitonic sort, descending, 2048 keys in shared memory
// ---------------------------------------------------------------------------
__global__ void k2_sort() {
    __shared__ unsigned long long s[NPAD];
    int b = blockIdx.x;
    int tid = threadIdx.x;  // 1024 threads
    int t2 = tid + 1024;
    s[tid] = (tid < NN) ? g_key[b * NPAD + tid] : 0ull;
    s[t2] = (t2 < NN) ? g_key[b * NPAD + t2] : 0ull;
    __syncthreads();

    for (int k = 2; k <= NPAD; k <<= 1) {
        for (int j = k >> 1; j > 0; j >>= 1) {
#pragma unroll
            for (int e = 0; e < 2; ++e) {
                int i = tid + e * 1024;
                int ixj = i ^ j;
                if (ixj > i) {
                    unsigned long long a = s[i];
                    unsigned long long c = s[ixj];
                    bool desc = ((i & k) == 0);
                    if (desc ? (a < c) : (a > c)) {
                        s[i] = c;
                        s[ixj] = a;
                    }
                }
            }
            __syncthreads();
        }
    }
    g_key[b * NPAD + tid] = s[tid];
    g_key[b * NPAD + t2] = s[t2];
}

// ---------------------------------------------------------------------------
// K3: greedy per-class NMS (class-offset trick), one warp per batch.
// Early exit at 100 keeps (provably equivalent to reference output).
// Writes det rows [MAXI,6] directly.
// ---------------------------------------------------------------------------
__global__ void k3_nms(float* __restrict__ det) {
    int b = blockIdx.x;
    int lane = threadIdx.x;  // 32 threads
    __shared__ float ky1[MAXI], kx1[MAXI], ky2[MAXI], kx2[MAXI], kar[MAXI];

    int kc = 0;
    for (int i = 0; i < NN; ++i) {
        unsigned long long key = g_key[b * NPAD + i];
        unsigned sb = (unsigned)(key >> 32);
        if (sb == 0u) break;  // rest are invalid
        int idx = (int)(0xFFFFFFFFu - (unsigned)(key & 0xFFFFFFFFull));
        float score = __uint_as_float(sb);
        int gi = b * NN + idx;
        float y1 = g_box[gi * 4 + 0];
        float x1 = g_box[gi * 4 + 1];
        float y2 = g_box[gi * 4 + 2];
        float x2 = g_box[gi * 4 + 3];
        float cf = (float)g_cls[gi];
        // offset boxes exactly as reference (area from offset coords)
        float oy1 = y1 + 2.0f * cf;
        float ox1 = x1 + 2.0f * cf;
        float oy2 = y2 + 2.0f * cf;
        float ox2 = x2 + 2.0f * cf;
        float ar = (oy2 - oy1) * (ox2 - ox1);

        bool sup = false;
        for (int j = lane; j < kc; j += 32) {
            float yy1 = fmaxf(oy1, ky1[j]);
            float xx1 = fmaxf(ox1, kx1[j]);
            float yy2 = fminf(oy2, ky2[j]);
            float xx2 = fminf(ox2, kx2[j]);
            float inter = fmaxf(yy2 - yy1, 0.0f) * fmaxf(xx2 - xx1, 0.0f);
            float uni = ar + kar[j] - inter;
            float iou = inter / fmaxf(uni, 1e-12f);
            if (iou > 0.3f) sup = true;
        }
        if (!__any_sync(0xffffffffu, sup)) {
            if (lane == 0) {
                ky1[kc] = oy1; kx1[kc] = ox1; ky2[kc] = oy2; kx2[kc] = ox2;
                kar[kc] = ar;
                float* dr = det + (b * MAXI + kc) * 6;
                dr[0] = y1; dr[1] = x1; dr[2] = y2; dr[3] = x2;
                dr[4] = cf; dr[5] = score;
            }
            kc++;
            __syncwarp();
            if (kc == MAXI) break;
        }
    }
    // zero-fill remaining det rows
    for (int t = lane; t < (MAXI - kc) * 6; t += 32)
        det[(b * MAXI + kc) * 6 + t] = 0.0f;
}

// ---------------------------------------------------------------------------
// K4: attention mask [B,H,W]. One block per (row,batch); compact active
// x-intervals for this row, then each thread covers one column.
// Zero det rows self-exclude (ys>=0 && ys<0 is false).
// ---------------------------------------------------------------------------
__global__ void k4_mask(const float* __restrict__ det, float* __restrict__ mask) {
    int h = blockIdx.x;
    int b = blockIdx.y;
    int w = threadIdx.x;  // 512 threads
    __shared__ float ax1[MAXI], ax2[MAXI];
    __shared__ int nact;
    if (w == 0) nact = 0;
    __syncthreads();

    if (w < MAXI) {
        const float* dr = det + (b * MAXI + w) * 6;
        float y1 = dr[0], x1 = dr[1], y2 = dr[2], x2 = dr[3];
        float ys = ((float)h + 0.5f) * (1.0f / 512.0f);  // exact, == /512
        if (ys >= y1 && ys < y2) {
            int p = atomicAdd(&nact, 1);
            ax1[p] = x1;
            ax2[p] = x2;
        }
    }
    __syncthreads();

    float xs = ((float)w + 0.5f) * (1.0f / 512.0f);
    float out = 0.0f;
    int na = nact;
    for (int j = 0; j < na; ++j) {
        if (xs >= ax1[j] && xs < ax2[j]) { out = 1.0f; break; }
    }
    mask[((long long)b * HH + h) * WW + w] = out;
}

// ---------------------------------------------------------------------------
extern "C" void kernel_launch(void* const* d_in, const int* in_sizes, int n_in,
                              void* d_out, int out_size) {
    const float* rois = (const float*)d_in[0];
    const float* probs = (const float*)d_in[1];
    const float* deltas = (const float*)d_in[2];
    const float* stdv = (const float*)d_in[3];
    float* det = (float*)d_out;                       // [B,100,6] = 4800 floats
    float* mask = (float*)d_out + BB * MAXI * 6;      // [B,512,512]

    k1_refine<<<(BB * NN + 255) / 256, 256>>>(rois, probs, deltas, stdv);
    k2_sort<<<BB, 1024>>>();
    k3_nms<<<BB, 32>>>(det);
    dim3 grid(HH, BB);
    k4_mask<<<grid, WW>>>(det, mask);
}

// round 2
// speedup vs baseline: 1.4698x; 1.4698x over previous
#include <cuda_runtime.h>

#define BB 8
#define NN 2000
#define CC 81
#define NPAD 2048
#define MAXI 100
#define HH 512
#define WW 512

// scratch (device globals: no allocation allowed)
__device__ float4 g_box4[BB * NN];
__device__ int g_cls[BB * NN];
__device__ unsigned long long g_key[BB * NPAD];

// ---------------------------------------------------------------------------
// K1: per-proposal argmax class, score, refined+clipped box, sort key
// ---------------------------------------------------------------------------
__global__ void k1_refine(const float* __restrict__ rois,
                          const float* __restrict__ probs,
                          const float* __restrict__ deltas,
                          const float* __restrict__ stdv) {
    int t = blockIdx.x * blockDim.x + threadIdx.x;
    if (t >= BB * NN) return;

    const float* p = probs + (long long)t * CC;
    float best = p[0];
    int bc = 0;
    for (int c = 1; c < CC; ++c) {
        float v = p[c];
        if (v > best) { best = v; bc = c; }  // strict > == first max (jnp.argmax)
    }

    // deltas row is 16B aligned: byte offset = (t*CC+bc)*16
    float4 dd = *(const float4*)(deltas + ((long long)t * CC + bc) * 4);
    float dy = dd.x * stdv[0];
    float dx = dd.y * stdv[1];
    float dh = dd.z * stdv[2];
    float dw = dd.w * stdv[3];

    const float* r = rois + t * 4;
    float y1 = r[0], x1 = r[1], y2 = r[2], x2 = r[3];
    float h = y2 - y1, w = x2 - x1;
    float cy = y1 + 0.5f * h + dy * h;
    float cx = x1 + 0.5f * w + dx * w;
    h = h * expf(dh);
    w = w * expf(dw);
    float4 nb;
    nb.x = fminf(fmaxf(cy - 0.5f * h, 0.0f), 1.0f);
    nb.y = fminf(fmaxf(cx - 0.5f * w, 0.0f), 1.0f);
    nb.z = fminf(fmaxf(cy + 0.5f * h, 0.0f), 1.0f);
    nb.w = fminf(fmaxf(cx + 0.5f * w, 0.0f), 1.0f);

    g_box4[t] = nb;
    g_cls[t] = bc;

    int b = t / NN;
    int n = t - b * NN;
    bool valid = (bc > 0) && (best >= 0.05f);
    // score bits monotone for nonneg floats; (0xFFFFFFFF - n) => stable tie
    // break (smaller index first) under a DESCENDING sort.
    unsigned long long key =
        valid ? ((((unsigned long long)__float_as_uint(best)) << 32) |
                 (unsigned long long)(0xFFFFFFFFu - (unsigned)n))
              : 0ull;
    g_key[b * NPAD + n] = key;
}

// ---------------------------------------------------------------------------
// bitonic compare-exchange via shfl (register phase, j <= 16)
// ---------------------------------------------------------------------------
__device__ __forceinline__ void cswap(unsigned long long& v, int i, int j, int k) {
    unsigned long long pv = __shfl_xor_sync(0xffffffffu, v, j);
    bool take_max = (((i & k) == 0) ^ ((i & j) != 0));
    bool pick = take_max ? (pv > v) : (pv < v);
    if (pick) v = pv;
}

// ---------------------------------------------------------------------------
// K23: per-batch hybrid bitonic sort (desc) + greedy per-class NMS.
// One block per batch, 1024 threads. After sort, top-1024 candidate boxes are
// gathered into shared; warp 0 runs the serial greedy loop with the <=100
// kept (offset) boxes held in registers distributed across lanes.
// Early exit at 100 keeps (equivalent to reference: top_k(100) of kept ==
// first 100 kept in descending order; the per-class cap can only trigger
// after >=100 total keeps).
// ---------------------------------------------------------------------------
__global__ void __launch_bounds__(1024) k23_sortnms(float* __restrict__ det) {
    __shared__ unsigned long long s[NPAD];
    __shared__ float sy1[1024], sx1[1024], sy2[1024], sx2[1024], ssc[1024];
    __shared__ int scl[1024];
    __shared__ int s_kc;

    int b = blockIdx.x;
    int tid = threadIdx.x;
    int lane = tid & 31;
    int wrp = tid >> 5;
    int t2 = tid + 1024;

    s[tid] = (tid < NN) ? g_key[b * NPAD + tid] : 0ull;
    s[t2] = (t2 < NN) ? g_key[b * NPAD + t2] : 0ull;
    __syncthreads();

    // warp 'wrp' owns elements [64*wrp, 64*wrp+64)
    int i0 = wrp * 64 + lane;
    int i1 = wrp * 64 + 32 + lane;

    // stages k=2..32 entirely in registers (all j<=16)
    {
        unsigned long long r0 = s[i0], r1 = s[i1];
#pragma unroll
        for (int k = 2; k <= 32; k <<= 1) {
#pragma unroll
            for (int j = k >> 1; j > 0; j >>= 1) {
                cswap(r0, i0, j, k);
                cswap(r1, i1, j, k);
            }
        }
        s[i0] = r0;
        s[i1] = r1;
    }
    __syncthreads();

    for (int k = 64; k <= NPAD; k <<= 1) {
        for (int j = k >> 1; j >= 32; j >>= 1) {
#pragma unroll
            for (int e = 0; e < 2; ++e) {
                int i = tid + e * 1024;
                int ixj = i ^ j;
                if (ixj > i) {
                    unsigned long long a = s[i];
                    unsigned long long c = s[ixj];
                    bool desc = ((i & k) == 0);
                    if (desc ? (a < c) : (a > c)) {
                        s[i] = c;
                        s[ixj] = a;
                    }
                }
            }
            __syncthreads();
        }
        // register tail: j = 16..1
        unsigned long long r0 = s[i0], r1 = s[i1];
#pragma unroll
        for (int j = 16; j > 0; j >>= 1) {
            cswap(r0, i0, j, k);
            cswap(r1, i1, j, k);
        }
        s[i0] = r0;
        s[i1] = r1;
        __syncthreads();
    }

    // gather top-1024 sorted candidates into shared
    {
        unsigned long long key = s[tid];
        unsigned sb = (unsigned)(key >> 32);
        if (sb) {
            int idx = (int)(0xFFFFFFFFu - (unsigned)(key & 0xFFFFFFFFull));
            int gi = b * NN + idx;
            float4 bx = g_box4[gi];
            sy1[tid] = bx.x;
            sx1[tid] = bx.y;
            sy2[tid] = bx.z;
            sx2[tid] = bx.w;
            scl[tid] = g_cls[gi];
            ssc[tid] = __uint_as_float(sb);
        }
    }
    __syncthreads();

    if (wrp == 0) {
        // kept offset-boxes in registers: lane holds slots {lane, lane+32, ...}
        float ky1[4], kx1[4], ky2[4], kx2[4], kar[4];
        int kc = 0;
        for (int i = 0; i < NN; ++i) {
            unsigned long long key = s[i];
            unsigned sb = (unsigned)(key >> 32);
            if (!sb) break;  // remainder invalid
            float y1, x1, y2, x2, cf, score;
            if (i < 1024) {
                y1 = sy1[i]; x1 = sx1[i]; y2 = sy2[i]; x2 = sx2[i];
                cf = (float)scl[i];
                score = ssc[i];
            } else {  // rare fallback
                int idx = (int)(0xFFFFFFFFu - (unsigned)(key & 0xFFFFFFFFull));
                int gi = b * NN + idx;
                float4 bx = g_box4[gi];
                y1 = bx.x; x1 = bx.y; y2 = bx.z; x2 = bx.w;
                cf = (float)g_cls[gi];
                score = __uint_as_float(sb);
            }
            float oy1 = y1 + 2.0f * cf;
            float ox1 = x1 + 2.0f * cf;
            float oy2 = y2 + 2.0f * cf;
            float ox2 = x2 + 2.0f * cf;
            float ar = (oy2 - oy1) * (ox2 - ox1);

            bool sup = false;
#pragma unroll
            for (int sl = 0; sl < 4; ++sl) {
                int j = sl * 32 + lane;
                if (j < kc) {
                    float yy1 = fmaxf(oy1, ky1[sl]);
                    float xx1 = fmaxf(ox1, kx1[sl]);
                    float yy2 = fminf(oy2, ky2[sl]);
                    float xx2 = fminf(ox2, kx2[sl]);
                    float inter = fmaxf(yy2 - yy1, 0.0f) * fmaxf(xx2 - xx1, 0.0f);
                    float uni = ar + kar[sl] - inter;
                    float iou = inter / fmaxf(uni, 1e-12f);
                    sup |= (iou > 0.3f);
                }
            }
            if (!__any_sync(0xffffffffu, sup)) {
                int slot = kc >> 5;
                int ln = kc & 31;
                if (lane == ln) {
                    switch (slot) {
                        case 0: ky1[0] = oy1; kx1[0] = ox1; ky2[0] = oy2; kx2[0] = ox2; kar[0] = ar; break;
                        case 1: ky1[1] = oy1; kx1[1] = ox1; ky2[1] = oy2; kx2[1] = ox2; kar[1] = ar; break;
                        case 2: ky1[2] = oy1; kx1[2] = ox1; ky2[2] = oy2; kx2[2] = ox2; kar[2] = ar; break;
                        default: ky1[3] = oy1; kx1[3] = ox1; ky2[3] = oy2; kx2[3] = ox2; kar[3] = ar; break;
                    }
                    float* dr = det + (b * MAXI + kc) * 6;
                    dr[0] = y1; dr[1] = x1; dr[2] = y2; dr[3] = x2;
                    dr[4] = cf; dr[5] = score;
                }
                kc++;
                if (kc == MAXI) break;
            }
        }
        if (lane == 0) s_kc = kc;
    }
    __syncthreads();
    int kc = s_kc;
    for (int t = tid; t < (MAXI - kc) * 6; t += 1024)
        det[(b * MAXI + kc) * 6 + t] = 0.0f;
}

// ---------------------------------------------------------------------------
// K4: rect-fill. mask pre-zeroed by cudaMemsetAsync; one block per (det row,
// batch) writes 1.0f over its covered pixels (idempotent, race-safe).
// Exact per-pixel predicates applied inside a conservatively widened rect.
// ---------------------------------------------------------------------------
__global__ void k4_fill(const float* __restrict__ det, float* __restrict__ mask) {
    int d = blockIdx.x;
    int b = blockIdx.y;
    const float* dr = det + (b * MAXI + d) * 6;
    float y1 = dr[0], x1 = dr[1], y2 = dr[2], x2 = dr[3];
    if (!(y2 > y1) || !(x2 > x1)) return;  // empty / padded rows

    const float inv = 1.0f / 512.0f;
    int hs = max(0, (int)floorf(512.0f * y1 - 0.5f));
    int he = min(HH - 1, (int)ceilf(512.0f * y2 - 0.5f));
    int ws = max(0, (int)floorf(512.0f * x1 - 0.5f));
    int we = min(WW - 1, (int)ceilf(512.0f * x2 - 0.5f));

    for (int h = hs; h <= he; ++h) {
        float ys = ((float)h + 0.5f) * inv;
        if (!(ys >= y1 && ys < y2)) continue;
        float* row = mask + ((long long)b * HH + h) * WW;
        for (int x = ws + threadIdx.x; x <= we; x += blockDim.x) {
            float xs = ((float)x + 0.5f) * inv;
            if (xs >= x1 && xs < x2) row[x] = 1.0f;
        }
    }
}

// ---------------------------------------------------------------------------
extern "C" void kernel_launch(void* const* d_in, const int* in_sizes, int n_in,
                              void* d_out, int out_size) {
    const float* rois = (const float*)d_in[0];
    const float* probs = (const float*)d_in[1];
    const float* deltas = (const float*)d_in[2];
    const float* stdv = (const float*)d_in[3];
    float* det = (float*)d_out;                   // [B,100,6] = 4800 floats
    float* mask = (float*)d_out + BB * MAXI * 6;  // [B,512,512]

    k1_refine<<<(BB * NN + 127) / 128, 128>>>(rois, probs, deltas, stdv);
    k23_sortnms<<<BB, 1024>>>(det);
    cudaMemsetAsync(mask, 0, (size_t)BB * HH * WW * sizeof(float));
    dim3 grid(MAXI, BB);
    k4_fill<<<grid, 128>>>(det, mask);
}

// round 3
// speedup vs baseline: 2.3986x; 1.6319x over previous
#include <cuda_runtime.h>

#define BB 8
#define NN 2000
#define CC 81
#define NPAD 2048
#define MAXI 100
#define HH 512
#define WW 512
#define MSEL 256

// scratch (device globals: no allocation allowed)
__device__ float4 g_box4[BB * NN];
__device__ int g_cls[BB * NN];
__device__ unsigned long long g_key[BB * NPAD];

// ---------------------------------------------------------------------------
// K1: warp per proposal. Coalesced prob reads + shfl argmax reduction.
// ---------------------------------------------------------------------------
__global__ void k1_refine(const float* __restrict__ rois,
                          const float* __restrict__ probs,
                          const float* __restrict__ deltas,
                          const float* __restrict__ stdv) {
    int gw = (blockIdx.x * blockDim.x + threadIdx.x) >> 5;
    int lane = threadIdx.x & 31;
    if (gw >= BB * NN) return;

    const float* p = probs + (long long)gw * CC;
    float best = p[lane];
    int bc = lane;
    { float v = p[lane + 32]; if (v > best) { best = v; bc = lane + 32; } }
    if (lane + 64 < CC) { float v = p[lane + 64]; if (v > best) { best = v; bc = lane + 64; } }
    // reduce to lane 0: higher score wins; tie -> lower class index (first max)
#pragma unroll
    for (int o = 16; o; o >>= 1) {
        float ov = __shfl_down_sync(0xffffffffu, best, o);
        int oc = __shfl_down_sync(0xffffffffu, bc, o);
        if (ov > best || (ov == best && oc < bc)) { best = ov; bc = oc; }
    }

    if (lane == 0) {
        float4 dd = *(const float4*)(deltas + ((long long)gw * CC + bc) * 4);
        float dy = dd.x * stdv[0];
        float dx = dd.y * stdv[1];
        float dh = dd.z * stdv[2];
        float dw = dd.w * stdv[3];

        float4 rr = *(const float4*)(rois + gw * 4);
        float y1 = rr.x, x1 = rr.y, y2 = rr.z, x2 = rr.w;
        float h = y2 - y1, w = x2 - x1;
        float cy = y1 + 0.5f * h + dy * h;
        float cx = x1 + 0.5f * w + dx * w;
        h = h * expf(dh);
        w = w * expf(dw);
        float4 nb;
        nb.x = fminf(fmaxf(cy - 0.5f * h, 0.0f), 1.0f);
        nb.y = fminf(fmaxf(cx - 0.5f * w, 0.0f), 1.0f);
        nb.z = fminf(fmaxf(cy + 0.5f * h, 0.0f), 1.0f);
        nb.w = fminf(fmaxf(cx + 0.5f * w, 0.0f), 1.0f);

        g_box4[gw] = nb;
        g_cls[gw] = bc;

        int b = gw / NN;
        int n = gw - b * NN;
        bool valid = (bc > 0) && (best >= 0.05f);
        unsigned long long key =
            valid ? ((((unsigned long long)__float_as_uint(best)) << 32) |
                     (unsigned long long)(0xFFFFFFFFu - (unsigned)n))
                  : 0ull;
        g_key[b * NPAD + n] = key;
    }
}

// ---------------------------------------------------------------------------
__device__ __forceinline__ void cswap(unsigned long long& v, int i, int j, int k) {
    unsigned long long pv = __shfl_xor_sync(0xffffffffu, v, j);
    bool take_max = (((i & k) == 0) ^ ((i & j) != 0));
    bool pick = take_max ? (pv > v) : (pv < v);
    if (pick) v = pv;
}

// ---------------------------------------------------------------------------
// K23: hybrid bitonic sort (desc) + matrix NMS.
// Suppression matrix M (256x256 bits) built by ballots; greedy scan on one
// thread with the suppressed-mask in 8 registers. Early exit at 100 keeps
// (equivalent to reference). Warp-cooperative fallback beyond 256 cands.
// ---------------------------------------------------------------------------
__global__ void __launch_bounds__(1024) k23_sortnms(float* __restrict__ det) {
    __shared__ unsigned long long s[NPAD];            // keys; [0..1023] reused as M
    __shared__ float sy1[1024], sx1[1024], sy2[1024], sx2[1024], ssc[1024];
    __shared__ int scl[1024];
    __shared__ float ky1[MAXI], kx1[MAXI], ky2[MAXI], kx2[MAXI], kar[MAXI];
    __shared__ unsigned svalid[MSEL / 32];
    __shared__ int s_kc;

    unsigned* M = (unsigned*)s;  // M[i*8 + w], i<256, w<8 -> 8KB = s[0..1023]

    int b = blockIdx.x;
    int tid = threadIdx.x;
    int lane = tid & 31;
    int wrp = tid >> 5;
    int t2 = tid + 1024;

    s[tid] = (tid < NN) ? g_key[b * NPAD + tid] : 0ull;
    s[t2] = (t2 < NN) ? g_key[b * NPAD + t2] : 0ull;
    __syncthreads();

    int i0 = wrp * 64 + lane;
    int i1 = wrp * 64 + 32 + lane;
    {   // stages k=2..32 in registers
        unsigned long long r0 = s[i0], r1 = s[i1];
#pragma unroll
        for (int k = 2; k <= 32; k <<= 1)
#pragma unroll
            for (int j = k >> 1; j > 0; j >>= 1) { cswap(r0, i0, j, k); cswap(r1, i1, j, k); }
        s[i0] = r0;
        s[i1] = r1;
    }
    __syncthreads();

    for (int k = 64; k <= NPAD; k <<= 1) {
        for (int j = k >> 1; j >= 32; j >>= 1) {
#pragma unroll
            for (int e = 0; e < 2; ++e) {
                int i = tid + e * 1024;
                int ixj = i ^ j;
                if (ixj > i) {
                    unsigned long long a = s[i], c = s[ixj];
                    bool desc = ((i & k) == 0);
                    if (desc ? (a < c) : (a > c)) { s[i] = c; s[ixj] = a; }
                }
            }
            __syncthreads();
        }
        unsigned long long r0 = s[i0], r1 = s[i1];
#pragma unroll
        for (int j = 16; j > 0; j >>= 1) { cswap(r0, i0, j, k); cswap(r1, i1, j, k); }
        s[i0] = r0;
        s[i1] = r1;
        __syncthreads();
    }

    // gather top-1024 candidates into shared; ssc<0 marks invalid
    {
        unsigned long long key = s[tid];
        unsigned sb = (unsigned)(key >> 32);
        if (sb) {
            int idx = (int)(0xFFFFFFFFu - (unsigned)(key & 0xFFFFFFFFull));
            int gi = b * NN + idx;
            float4 bx = g_box4[gi];
            sy1[tid] = bx.x; sx1[tid] = bx.y; sy2[tid] = bx.z; sx2[tid] = bx.w;
            scl[tid] = g_cls[gi];
            ssc[tid] = __uint_as_float(sb);
        } else {
            ssc[tid] = -1.0f;
        }
    }
    __syncthreads();   // s[0..1023] dead from here -> M may overwrite

    // validity bitmask for first 256
    if (wrp < MSEL / 32) {
        unsigned vb = __ballot_sync(0xffffffffu, ssc[wrp * 32 + lane] > 0.0f);
        if (lane == 0) svalid[wrp] = vb;
    }

    // matrix build: warp handles column-word wcol for 64 rows starting at ib
    {
        int wcol = wrp & 7;
        int ib = (wrp >> 3) * 64;
        int j = wcol * 32 + lane;
        float cfj = (float)scl[j];
        float jy1 = sy1[j] + 2.0f * cfj;
        float jx1 = sx1[j] + 2.0f * cfj;
        float jy2 = sy2[j] + 2.0f * cfj;
        float jx2 = sx2[j] + 2.0f * cfj;
        float jar = (jy2 - jy1) * (jx2 - jx1);
        for (int i = ib; i < ib + 64; ++i) {
            float cfi = (float)scl[i];
            float iy1 = sy1[i] + 2.0f * cfi;
            float ix1 = sx1[i] + 2.0f * cfi;
            float iy2 = sy2[i] + 2.0f * cfi;
            float ix2 = sx2[i] + 2.0f * cfi;
            float iar = (iy2 - iy1) * (ix2 - ix1);
            float yy1 = fmaxf(iy1, jy1);
            float xx1 = fmaxf(ix1, jx1);
            float yy2 = fminf(iy2, jy2);
            float xx2 = fminf(ix2, jx2);
            float inter = fmaxf(yy2 - yy1, 0.0f) * fmaxf(xx2 - xx1, 0.0f);
            float uni = iar + jar - inter;
            float iou = inter / fmaxf(uni, 1e-12f);
            unsigned bal = __ballot_sync(0xffffffffu, iou > 0.3f);
            if (lane == 0) M[i * 8 + wcol] = bal;
        }
    }
    __syncthreads();

    // serial greedy on one thread; suppressed mask in 8 registers
    if (tid == 0) {
        unsigned r[8] = {0, 0, 0, 0, 0, 0, 0, 0};
        int kc = 0;
        bool done = false;
#pragma unroll
        for (int w = 0; w < 8; ++w) {
            if (!done) {
                unsigned vw = svalid[w];
                for (int bi = 0; bi < 32; ++bi) {
                    if (!((vw >> bi) & 1u)) { done = true; break; }
                    if (!((r[w] >> bi) & 1u)) {
                        int i = (w << 5) | bi;
                        float y1 = sy1[i], x1 = sx1[i], y2 = sy2[i], x2 = sx2[i];
                        float cf = (float)scl[i];
                        float* dr = det + (b * MAXI + kc) * 6;
                        dr[0] = y1; dr[1] = x1; dr[2] = y2; dr[3] = x2;
                        dr[4] = cf; dr[5] = ssc[i];
                        float oy1 = y1 + 2.0f * cf, ox1 = x1 + 2.0f * cf;
                        float oy2 = y2 + 2.0f * cf, ox2 = x2 + 2.0f * cf;
                        ky1[kc] = oy1; kx1[kc] = ox1; ky2[kc] = oy2; kx2[kc] = ox2;
                        kar[kc] = (oy2 - oy1) * (ox2 - ox1);
                        kc++;
                        if (kc == MAXI) { done = true; break; }
                        const unsigned* row = M + i * 8;
#pragma unroll
                        for (int k2 = 0; k2 < 8; ++k2) r[k2] |= row[k2];
                    }
                }
            }
        }
        s_kc = kc;
    }
    __syncthreads();

    // rare fallback: continue greedy beyond MSEL with warp 0
    if (wrp == 0 && s_kc < MAXI) {
        int kc = s_kc;
        for (int i = MSEL; i < NN && kc < MAXI; ++i) {
            float y1, x1, y2, x2, cf, score;
            bool valid;
            if (i < 1024) {
                score = ssc[i];
                valid = score > 0.0f;
                y1 = sy1[i]; x1 = sx1[i]; y2 = sy2[i]; x2 = sx2[i];
                cf = (float)scl[i];
            } else {
                unsigned long long key = s[i];
                unsigned sb = (unsigned)(key >> 32);
                valid = sb != 0u;
                score = __uint_as_float(sb);
                int idx = (int)(0xFFFFFFFFu - (unsigned)(key & 0xFFFFFFFFull));
                int gi = b * NN + idx;
                float4 bx = g_box4[gi];
                y1 = bx.x; x1 = bx.y; y2 = bx.z; x2 = bx.w;
                cf = (float)g_cls[gi];
            }
            if (!valid) break;
            float oy1 = y1 + 2.0f * cf, ox1 = x1 + 2.0f * cf;
            float oy2 = y2 + 2.0f * cf, ox2 = x2 + 2.0f * cf;
            float ar = (oy2 - oy1) * (ox2 - ox1);
            bool sup = false;
            for (int j = lane; j < kc; j += 32) {
                float yy1 = fmaxf(oy1, ky1[j]);
                float xx1 = fmaxf(ox1, kx1[j]);
                float yy2 = fminf(oy2, ky2[j]);
                float xx2 = fminf(ox2, kx2[j]);
                float inter = fmaxf(yy2 - yy1, 0.0f) * fmaxf(xx2 - xx1, 0.0f);
                float uni = ar + kar[j] - inter;
                float iou = inter / fmaxf(uni, 1e-12f);
                sup |= (iou > 0.3f);
            }
            if (!__any_sync(0xffffffffu, sup)) {
                if (lane == 0) {
                    ky1[kc] = oy1; kx1[kc] = ox1; ky2[kc] = oy2; kx2[kc] = ox2;
                    kar[kc] = ar;
                    float* dr = det + (b * MAXI + kc) * 6;
                    dr[0] = y1; dr[1] = x1; dr[2] = y2; dr[3] = x2;
                    dr[4] = cf; dr[5] = score;
                }
                kc++;
            }
            __syncwarp();
        }
        if (lane == 0) s_kc = kc;
    }
    __syncthreads();

    int kc = s_kc;
    for (int t = tid; t < (MAXI - kc) * 6; t += 1024)
        det[(b * MAXI + kc) * 6 + t] = 0.0f;
}

// ---------------------------------------------------------------------------
// K4: fused mask (no memset). One block per (row,batch); compact active
// x-intervals, then each thread writes one float4 (4 pixels).
// ---------------------------------------------------------------------------
__global__ void k4_mask(const float* __restrict__ det, float* __restrict__ mask) {
    int h = blockIdx.x;
    int b = blockIdx.y;
    int tid = threadIdx.x;  // 128 threads
    __shared__ float ax1[MAXI], ax2[MAXI];
    __shared__ int nact;
    if (tid == 0) nact = 0;
    __syncthreads();

    if (tid < MAXI) {
        const float* dr = det + (b * MAXI + tid) * 6;
        float y1 = dr[0], x1 = dr[1], y2 = dr[2], x2 = dr[3];
        float ys = ((float)h + 0.5f) * (1.0f / 512.0f);
        if (ys >= y1 && ys < y2) {
            int p = atomicAdd(&nact, 1);
            ax1[p] = x1;
            ax2[p] = x2;
        }
    }
    __syncthreads();

    int na = nact;
    float xb = (float)(tid * 4);
    float xs0 = (xb + 0.5f) * (1.0f / 512.0f);
    float xs1 = (xb + 1.5f) * (1.0f / 512.0f);
    float xs2 = (xb + 2.5f) * (1.0f / 512.0f);
    float xs3 = (xb + 3.5f) * (1.0f / 512.0f);
    float4 o = make_float4(0.f, 0.f, 0.f, 0.f);
    for (int j = 0; j < na; ++j) {
        float a = ax1[j], c = ax2[j];
        if (xs0 >= a && xs0 < c) o.x = 1.0f;
        if (xs1 >= a && xs1 < c) o.y = 1.0f;
        if (xs2 >= a && xs2 < c) o.z = 1.0f;
        if (xs3 >= a && xs3 < c) o.w = 1.0f;
    }
    ((float4*)(mask + ((long long)(b * HH + h)) * WW))[tid] = o;
}

// ---------------------------------------------------------------------------
extern "C" void kernel_launch(void* const* d_in, const int* in_sizes, int n_in,
                              void* d_out, int out_size) {
    const float* rois = (const float*)d_in[0];
    const float* probs = (const float*)d_in[1];
    const float* deltas = (const float*)d_in[2];
    const float* stdv = (const float*)d_in[3];
    float* det = (float*)d_out;                   // [B,100,6]
    float* mask = (float*)d_out + BB * MAXI * 6;  // [B,512,512]

    k1_refine<<<(BB * NN * 32 + 255) / 256, 256>>>(rois, probs, deltas, stdv);
    k23_sortnms<<<BB, 1024>>>(det);
    dim3 grid(HH, BB);
    k4_mask<<<grid, 128>>>(det, mask);
}

// round 4
// speedup vs baseline: 2.7253x; 1.1362x over previous
#include <cuda_runtime.h>

#define BB 8
#define NN 2000
#define CC 81
#define NPAD 2048
#define MAXI 100
#define HH 512
#define WW 512
#define MSEL 256

// scratch (device globals: no allocation allowed)
__device__ float4 g_box4[BB * NN];
__device__ int g_cls[BB * NN];
__device__ unsigned long long g_key[BB * NPAD];

// ---------------------------------------------------------------------------
// K1: warp per proposal. Coalesced prob reads + shfl argmax reduction.
// ---------------------------------------------------------------------------
__global__ void k1_refine(const float* __restrict__ rois,
                          const float* __restrict__ probs,
                          const float* __restrict__ deltas,
                          const float* __restrict__ stdv) {
    int gw = (blockIdx.x * blockDim.x + threadIdx.x) >> 5;
    int lane = threadIdx.x & 31;
    if (gw >= BB * NN) return;

    const float* p = probs + (long long)gw * CC;
    float best = p[lane];
    int bc = lane;
    { float v = p[lane + 32]; if (v > best) { best = v; bc = lane + 32; } }
    if (lane + 64 < CC) { float v = p[lane + 64]; if (v > best) { best = v; bc = lane + 64; } }
#pragma unroll
    for (int o = 16; o; o >>= 1) {
        float ov = __shfl_down_sync(0xffffffffu, best, o);
        int oc = __shfl_down_sync(0xffffffffu, bc, o);
        if (ov > best || (ov == best && oc < bc)) { best = ov; bc = oc; }
    }

    if (lane == 0) {
        float4 dd = *(const float4*)(deltas + ((long long)gw * CC + bc) * 4);
        float dy = dd.x * stdv[0];
        float dx = dd.y * stdv[1];
        float dh = dd.z * stdv[2];
        float dw = dd.w * stdv[3];

        float4 rr = *(const float4*)(rois + gw * 4);
        float y1 = rr.x, x1 = rr.y, y2 = rr.z, x2 = rr.w;
        float h = y2 - y1, w = x2 - x1;
        float cy = y1 + 0.5f * h + dy * h;
        float cx = x1 + 0.5f * w + dx * w;
        h = h * expf(dh);
        w = w * expf(dw);
        float4 nb;
        nb.x = fminf(fmaxf(cy - 0.5f * h, 0.0f), 1.0f);
        nb.y = fminf(fmaxf(cx - 0.5f * w, 0.0f), 1.0f);
        nb.z = fminf(fmaxf(cy + 0.5f * h, 0.0f), 1.0f);
        nb.w = fminf(fmaxf(cx + 0.5f * w, 0.0f), 1.0f);

        g_box4[gw] = nb;
        g_cls[gw] = bc;

        int b = gw / NN;
        int n = gw - b * NN;
        bool valid = (bc > 0) && (best >= 0.05f);
        unsigned long long key =
            valid ? ((((unsigned long long)__float_as_uint(best)) << 32) |
                     (unsigned long long)(0xFFFFFFFFu - (unsigned)n))
                  : 0ull;
        g_key[b * NPAD + n] = key;
    }
}

// ---------------------------------------------------------------------------
__device__ __forceinline__ void cswap(unsigned long long& v, int i, int j, int k) {
    unsigned long long pv = __shfl_xor_sync(0xffffffffu, v, j);
    bool take_max = (((i & k) == 0) ^ ((i & j) != 0));
    bool pick = take_max ? (pv > v) : (pv < v);
    if (pick) v = pv;
}

// ---------------------------------------------------------------------------
// K23: hybrid bitonic sort (desc) + 256x256 suppression matrix +
// warp-parallel fixpoint greedy (exact sequential-greedy semantics).
// Early exit at 100 keeps (== reference). Serial fallback if >256 candidates
// are needed (sorted keys preserved).
// ---------------------------------------------------------------------------
__global__ void __launch_bounds__(1024) k23_sortnms(float* __restrict__ det) {
    __shared__ unsigned long long s[NPAD];  // 16KB, preserved for fallback
    __shared__ float sy1[MSEL], sx1[MSEL], sy2[MSEL], sx2[MSEL], ssc[MSEL];
    __shared__ int scl[MSEL];
    __shared__ unsigned Mm[MSEL * 8];       // 8KB suppression matrix
    __shared__ float ky1[MAXI], kx1[MAXI], ky2[MAXI], kx2[MAXI], kar[MAXI];
    __shared__ int s_kc;
    __shared__ int s_fb;

    int b = blockIdx.x;
    int tid = threadIdx.x;
    int lane = tid & 31;
    int wrp = tid >> 5;
    int t2 = tid + 1024;

    s[tid] = (tid < NN) ? g_key[b * NPAD + tid] : 0ull;
    s[t2] = (t2 < NN) ? g_key[b * NPAD + t2] : 0ull;
    __syncthreads();

    int i0 = wrp * 64 + lane;
    int i1 = wrp * 64 + 32 + lane;
    {   // stages k=2..32 in registers
        unsigned long long r0 = s[i0], r1 = s[i1];
#pragma unroll
        for (int k = 2; k <= 32; k <<= 1)
#pragma unroll
            for (int j = k >> 1; j > 0; j >>= 1) { cswap(r0, i0, j, k); cswap(r1, i1, j, k); }
        s[i0] = r0;
        s[i1] = r1;
    }
    __syncthreads();

    for (int k = 64; k <= NPAD; k <<= 1) {
        for (int j = k >> 1; j >= 32; j >>= 1) {
#pragma unroll
            for (int e = 0; e < 2; ++e) {
                int i = tid + e * 1024;
                int ixj = i ^ j;
                if (ixj > i) {
                    unsigned long long a = s[i], c = s[ixj];
                    bool desc = ((i & k) == 0);
                    if (desc ? (a < c) : (a > c)) { s[i] = c; s[ixj] = a; }
                }
            }
            __syncthreads();
        }
        unsigned long long r0 = s[i0], r1 = s[i1];
#pragma unroll
        for (int j = 16; j > 0; j >>= 1) { cswap(r0, i0, j, k); cswap(r1, i1, j, k); }
        s[i0] = r0;
        s[i1] = r1;
        __syncthreads();
    }

    // gather top-256 candidates into shared
    if (tid < MSEL) {
        unsigned long long key = s[tid];
        unsigned sb = (unsigned)(key >> 32);
        if (sb) {
            int idx = (int)(0xFFFFFFFFu - (unsigned)(key & 0xFFFFFFFFull));
            int gi = b * NN + idx;
            float4 bx = g_box4[gi];
            sy1[tid] = bx.x; sx1[tid] = bx.y; sy2[tid] = bx.z; sx2[tid] = bx.w;
            scl[tid] = g_cls[gi];
            ssc[tid] = __uint_as_float(sb);
        } else {
            sy1[tid] = 0.f; sx1[tid] = 0.f; sy2[tid] = 0.f; sx2[tid] = 0.f;
            scl[tid] = 0;
            ssc[tid] = -1.0f;
        }
    }
    __syncthreads();

    // matrix build: warp -> column-word (wrp&7) for 64 rows at ((wrp>>3)*64)
    {
        int wcol = wrp & 7;
        int ib = (wrp >> 3) * 64;
        int j = wcol * 32 + lane;
        float cfj = (float)scl[j];
        float jy1 = sy1[j] + 2.0f * cfj;
        float jx1 = sx1[j] + 2.0f * cfj;
        float jy2 = sy2[j] + 2.0f * cfj;
        float jx2 = sx2[j] + 2.0f * cfj;
        float jar = (jy2 - jy1) * (jx2 - jx1);
        for (int i = ib; i < ib + 64; ++i) {
            float cfi = (float)scl[i];
            float iy1 = sy1[i] + 2.0f * cfi;
            float ix1 = sx1[i] + 2.0f * cfi;
            float iy2 = sy2[i] + 2.0f * cfi;
            float ix2 = sx2[i] + 2.0f * cfi;
            float iar = (iy2 - iy1) * (ix2 - ix1);
            float yy1 = fmaxf(iy1, jy1);
            float xx1 = fmaxf(ix1, jx1);
            float yy2 = fminf(iy2, jy2);
            float xx2 = fminf(ix2, jx2);
            float inter = fmaxf(yy2 - yy1, 0.0f) * fmaxf(xx2 - xx1, 0.0f);
            float uni = iar + jar - inter;
            float iou = inter / fmaxf(uni, 1e-12f);
            unsigned bal = __ballot_sync(0xffffffffu, iou > 0.3f);
            if (lane == 0) Mm[i * 8 + wcol] = bal;
        }
    }
    __syncthreads();

    // warp-parallel greedy over 8 chunks of 32 candidates
    if (wrp == 0) {
        unsigned rem[8] = {0, 0, 0, 0, 0, 0, 0, 0};
        int kc = 0;
        bool done = false;
        unsigned lower = (1u << lane) - 1u;
        for (int c = 0; c < 8 && !done; ++c) {
            int i = c * 32 + lane;
            unsigned row[8];
#pragma unroll
            for (int w = 0; w < 8; ++w) row[w] = Mm[i * 8 + w];
            bool v = ssc[i] > 0.0f;
            bool psup = (rem[c] >> lane) & 1u;
            unsigned wchunk = row[c] & lower;  // same-chunk earlier (symmetry)

            bool k = v && !psup;
            unsigned km = __ballot_sync(0xffffffffu, k);
            for (int it = 0; it < 40; ++it) {
                bool kn = v && !psup && ((wchunk & km) == 0u);
                unsigned km2 = __ballot_sync(0xffffffffu, kn);
                if (km2 == km) break;
                km = km2;
            }
            k = (km >> lane) & 1u;

            if (km) {
                int cnt = __popc(km);
                int need = MAXI - kc;
                int pos = __popc(km & lower);
                if (k && pos < need) {
                    float* dr = det + (b * MAXI + kc + pos) * 6;
                    dr[0] = sy1[i]; dr[1] = sx1[i]; dr[2] = sy2[i]; dr[3] = sx2[i];
                    dr[4] = (float)scl[i]; dr[5] = ssc[i];
                }
                if (cnt >= need) {
                    kc = MAXI;
                    done = true;
                } else {
#pragma unroll
                    for (int w = 0; w < 8; ++w)
                        rem[w] |= __reduce_or_sync(0xffffffffu, k ? row[w] : 0u);
                    kc += cnt;
                }
            }
        }
        if (lane == 0) {
            s_kc = kc;
            // fallback needed only if not full AND valid candidates remain
            s_fb = (kc < MAXI && (unsigned)(s[MSEL] >> 32) != 0u) ? 1 : 0;
        }
    }
    __syncthreads();

    // rare fallback: serial warp NMS from scratch over full sorted list
    if (s_fb && wrp == 0) {
        int kc = 0;
        for (int i = 0; i < NN && kc < MAXI; ++i) {
            unsigned long long key = s[i];
            unsigned sb = (unsigned)(key >> 32);
            if (!sb) break;
            int idx = (int)(0xFFFFFFFFu - (unsigned)(key & 0xFFFFFFFFull));
            int gi = b * NN + idx;
            float4 bx = g_box4[gi];
            float y1 = bx.x, x1 = bx.y, y2 = bx.z, x2 = bx.w;
            float cf = (float)g_cls[gi];
            float score = __uint_as_float(sb);
            float oy1 = y1 + 2.0f * cf, ox1 = x1 + 2.0f * cf;
            float oy2 = y2 + 2.0f * cf, ox2 = x2 + 2.0f * cf;
            float ar = (oy2 - oy1) * (ox2 - ox1);
            bool sup = false;
            for (int j = lane; j < kc; j += 32) {
                float yy1 = fmaxf(oy1, ky1[j]);
                float xx1 = fmaxf(ox1, kx1[j]);
                float yy2 = fminf(oy2, ky2[j]);
                float xx2 = fminf(ox2, kx2[j]);
                float inter = fmaxf(yy2 - yy1, 0.0f) * fmaxf(xx2 - xx1, 0.0f);
                float uni = ar + kar[j] - inter;
                float iou = inter / fmaxf(uni, 1e-12f);
                sup |= (iou > 0.3f);
            }
            if (!__any_sync(0xffffffffu, sup)) {
                if (lane == 0) {
                    ky1[kc] = oy1; kx1[kc] = ox1; ky2[kc] = oy2; kx2[kc] = ox2;
                    kar[kc] = ar;
                    float* dr = det + (b * MAXI + kc) * 6;
                    dr[0] = y1; dr[1] = x1; dr[2] = y2; dr[3] = x2;
                    dr[4] = cf; dr[5] = score;
                }
                kc++;
            }
            __syncwarp();
        }
        if (lane == 0) s_kc = kc;
    }
    __syncthreads();

    int kc = s_kc;
    for (int t = tid; t < (MAXI - kc) * 6; t += 1024)
        det[(b * MAXI + kc) * 6 + t] = 0.0f;
}

// ---------------------------------------------------------------------------
// K4: mask. Block handles 8 rows of one batch; det loaded to shared once.
// ---------------------------------------------------------------------------
__global__ void k4_mask(const float* __restrict__ det, float* __restrict__ mask) {
    int b = blockIdx.y;
    int h0 = blockIdx.x * 8;
    int tid = threadIdx.x;  // 128 threads
    __shared__ float dy1[MAXI], dx1[MAXI], dy2[MAXI], dx2[MAXI];
    __shared__ float ax1[MAXI], ax2[MAXI];
    __shared__ int nact;

    if (tid < MAXI) {
        const float* dr = det + (b * MAXI + tid) * 6;
        float2 a = *(const float2*)(dr);      // y1,x1
        float2 c = *(const float2*)(dr + 2);  // y2,x2
        dy1[tid] = a.x; dx1[tid] = a.y; dy2[tid] = c.x; dx2[tid] = c.y;
    }
    __syncthreads();

    for (int r = 0; r < 8; ++r) {
        int h = h0 + r;
        if (tid == 0) nact = 0;
        __syncthreads();
        if (tid < MAXI) {
            float ys = ((float)h + 0.5f) * (1.0f / 512.0f);
            if (ys >= dy1[tid] && ys < dy2[tid]) {
                int p = atomicAdd(&nact, 1);
                ax1[p] = dx1[tid];
                ax2[p] = dx2[tid];
            }
        }
        __syncthreads();
        int na = nact;
        float xb = (float)(tid * 4);
        float xs0 = (xb + 0.5f) * (1.0f / 512.0f);
        float xs1 = (xb + 1.5f) * (1.0f / 512.0f);
        float xs2 = (xb + 2.5f) * (1.0f / 512.0f);
        float xs3 = (xb + 3.5f) * (1.0f / 512.0f);
        float4 o = make_float4(0.f, 0.f, 0.f, 0.f);
        for (int j = 0; j < na; ++j) {
            float a = ax1[j], c = ax2[j];
            if (xs0 >= a && xs0 < c) o.x = 1.0f;
            if (xs1 >= a && xs1 < c) o.y = 1.0f;
            if (xs2 >= a && xs2 < c) o.z = 1.0f;
            if (xs3 >= a && xs3 < c) o.w = 1.0f;
        }
        ((float4*)(mask + ((long long)(b * HH + h)) * WW))[tid] = o;
        __syncthreads();
    }
}

// ---------------------------------------------------------------------------
extern "C" void kernel_launch(void* const* d_in, const int* in_sizes, int n_in,
                              void* d_out, int out_size) {
    const float* rois = (const float*)d_in[0];
    const float* probs = (const float*)d_in[1];
    const float* deltas = (const float*)d_in[2];
    const float* stdv = (const float*)d_in[3];
    float* det = (float*)d_out;                   // [B,100,6]
    float* mask = (float*)d_out + BB * MAXI * 6;  // [B,512,512]

    k1_refine<<<(BB * NN * 32 + 255) / 256, 256>>>(rois, probs, deltas, stdv);
    k23_sortnms<<<BB, 1024>>>(det);
    dim3 grid(HH / 8, BB);
    k4_mask<<<grid, 128>>>(det, mask);
}

// round 5
// speedup vs baseline: 2.8448x; 1.0438x over previous
#include <cuda_runtime.h>

#define BB 8
#define NN 2000
#define CC 81
#define NPAD 2048
#define MAXI 100
#define HH 512
#define WW 512
#define MSEL 256

// scratch (device globals: no allocation allowed)
__device__ float4 g_box4[BB * NN];
__device__ int g_cls[BB * NN];
__device__ unsigned long long g_key[BB * NPAD];

// ---------------------------------------------------------------------------
// K1: warp handles 4 proposals. 12 independent coalesced loads (MLP=12),
// shfl argmax reductions, parallel epilogues on lanes 0-3.
// ---------------------------------------------------------------------------
__global__ void k1_refine(const float* __restrict__ rois,
                          const float* __restrict__ probs,
                          const float* __restrict__ deltas,
                          const float* __restrict__ stdv) {
    int gw4 = ((blockIdx.x * blockDim.x + threadIdx.x) >> 5) * 4;  // first proposal
    int lane = threadIdx.x & 31;
    if (gw4 >= BB * NN) return;

    float best[4];
    int bc[4];
#pragma unroll
    for (int q = 0; q < 4; ++q) {
        const float* p = probs + (long long)(gw4 + q) * CC;
        float b0 = p[lane];
        float b1 = p[lane + 32];
        float b2 = (lane + 64 < CC) ? p[lane + 64] : -1.0f;
        int c = lane;
        float bst = b0;
        if (b1 > bst) { bst = b1; c = lane + 32; }
        if (b2 > bst) { bst = b2; c = lane + 64; }
        best[q] = bst;
        bc[q] = c;
    }
#pragma unroll
    for (int q = 0; q < 4; ++q) {
#pragma unroll
        for (int o = 16; o; o >>= 1) {
            float ov = __shfl_down_sync(0xffffffffu, best[q], o);
            int oc = __shfl_down_sync(0xffffffffu, bc[q], o);
            if (ov > best[q] || (ov == best[q] && oc < bc[q])) { best[q] = ov; bc[q] = oc; }
        }
        // broadcast result to all lanes
        best[q] = __shfl_sync(0xffffffffu, best[q], 0);
        bc[q] = __shfl_sync(0xffffffffu, bc[q], 0);
    }

    if (lane < 4) {
        int gw = gw4 + lane;
        float bst = best[lane];
        int c = bc[lane];

        float4 dd = *(const float4*)(deltas + ((long long)gw * CC + c) * 4);
        float dy = dd.x * stdv[0];
        float dx = dd.y * stdv[1];
        float dh = dd.z * stdv[2];
        float dw = dd.w * stdv[3];

        float4 rr = *(const float4*)(rois + gw * 4);
        float y1 = rr.x, x1 = rr.y, y2 = rr.z, x2 = rr.w;
        float h = y2 - y1, w = x2 - x1;
        float cy = y1 + 0.5f * h + dy * h;
        float cx = x1 + 0.5f * w + dx * w;
        h = h * expf(dh);
        w = w * expf(dw);
        float4 nb;
        nb.x = fminf(fmaxf(cy - 0.5f * h, 0.0f), 1.0f);
        nb.y = fminf(fmaxf(cx - 0.5f * w, 0.0f), 1.0f);
        nb.z = fminf(fmaxf(cy + 0.5f * h, 0.0f), 1.0f);
        nb.w = fminf(fmaxf(cx + 0.5f * w, 0.0f), 1.0f);

        g_box4[gw] = nb;
        g_cls[gw] = c;

        int b = gw / NN;
        int n = gw - b * NN;
        bool valid = (c > 0) && (bst >= 0.05f);
        unsigned long long key =
            valid ? ((((unsigned long long)__float_as_uint(bst)) << 32) |
                     (unsigned long long)(0xFFFFFFFFu - (unsigned)n))
                  : 0ull;
        g_key[b * NPAD + n] = key;
    }
}

// ---------------------------------------------------------------------------
__device__ __forceinline__ void cswap(unsigned long long& v, int i, int j, int k) {
    unsigned long long pv = __shfl_xor_sync(0xffffffffu, v, j);
    bool take_max = (((i & k) == 0) ^ ((i & j) != 0));
    bool pick = take_max ? (pv > v) : (pv < v);
    if (pick) v = pv;
}

// ---------------------------------------------------------------------------
// K23: hybrid bitonic sort (desc) + 256x256 suppression matrix +
// warp-parallel fixpoint greedy (exact sequential-greedy semantics).
// Stages k<=64 run fully in registers (zero barriers).
// ---------------------------------------------------------------------------
__global__ void __launch_bounds__(1024) k23_sortnms(float* __restrict__ det) {
    __shared__ unsigned long long s[NPAD];  // 16KB, preserved for fallback
    __shared__ float sy1[MSEL], sx1[MSEL], sy2[MSEL], sx2[MSEL], ssc[MSEL];
    __shared__ int scl[MSEL];
    __shared__ unsigned Mm[MSEL * 8];       // 8KB suppression matrix
    __shared__ float ky1[MAXI], kx1[MAXI], ky2[MAXI], kx2[MAXI], kar[MAXI];
    __shared__ int s_kc;
    __shared__ int s_fb;

    int b = blockIdx.x;
    int tid = threadIdx.x;
    int lane = tid & 31;
    int wrp = tid >> 5;
    int t2 = tid + 1024;

    s[tid] = (tid < NN) ? g_key[b * NPAD + tid] : 0ull;
    s[t2] = (t2 < NN) ? g_key[b * NPAD + t2] : 0ull;
    __syncthreads();

    int i0 = wrp * 64 + lane;
    int i1 = wrp * 64 + 32 + lane;
    {   // stages k=2..64 entirely in registers
        unsigned long long r0 = s[i0], r1 = s[i1];
#pragma unroll
        for (int k = 2; k <= 32; k <<= 1)
#pragma unroll
            for (int j = k >> 1; j > 0; j >>= 1) { cswap(r0, i0, j, k); cswap(r1, i1, j, k); }
        // k=64, j=32: r0 <-> r1 exchange; direction constant per warp
        {
            bool desc = ((wrp & 1) == 0);
            if (desc ? (r0 < r1) : (r0 > r1)) {
                unsigned long long t = r0; r0 = r1; r1 = t;
            }
#pragma unroll
            for (int j = 16; j > 0; j >>= 1) { cswap(r0, i0, j, 64); cswap(r1, i1, j, 64); }
        }
        s[i0] = r0;
        s[i1] = r1;
    }
    __syncthreads();

    for (int k = 128; k <= NPAD; k <<= 1) {
        for (int j = k >> 1; j >= 32; j >>= 1) {
#pragma unroll
            for (int e = 0; e < 2; ++e) {
                int i = tid + e * 1024;
                int ixj = i ^ j;
                if (ixj > i) {
                    unsigned long long a = s[i], c = s[ixj];
                    bool desc = ((i & k) == 0);
                    if (desc ? (a < c) : (a > c)) { s[i] = c; s[ixj] = a; }
                }
            }
            __syncthreads();
        }
        unsigned long long r0 = s[i0], r1 = s[i1];
#pragma unroll
        for (int j = 16; j > 0; j >>= 1) { cswap(r0, i0, j, k); cswap(r1, i1, j, k); }
        s[i0] = r0;
        s[i1] = r1;
        __syncthreads();
    }

    // gather top-256 candidates into shared
    if (tid < MSEL) {
        unsigned long long key = s[tid];
        unsigned sb = (unsigned)(key >> 32);
        if (sb) {
            int idx = (int)(0xFFFFFFFFu - (unsigned)(key & 0xFFFFFFFFull));
            int gi = b * NN + idx;
            float4 bx = g_box4[gi];
            sy1[tid] = bx.x; sx1[tid] = bx.y; sy2[tid] = bx.z; sx2[tid] = bx.w;
            scl[tid] = g_cls[gi];
            ssc[tid] = __uint_as_float(sb);
        } else {
            sy1[tid] = 0.f; sx1[tid] = 0.f; sy2[tid] = 0.f; sx2[tid] = 0.f;
            scl[tid] = 0;
            ssc[tid] = -1.0f;
        }
    }
    __syncthreads();

    // matrix build: warp -> column-word (wrp&7) for 64 rows at ((wrp>>3)*64)
    {
        int wcol = wrp & 7;
        int ib = (wrp >> 3) * 64;
        int j = wcol * 32 + lane;
        float cfj = (float)scl[j];
        float jy1 = sy1[j] + 2.0f * cfj;
        float jx1 = sx1[j] + 2.0f * cfj;
        float jy2 = sy2[j] + 2.0f * cfj;
        float jx2 = sx2[j] + 2.0f * cfj;
        float jar = (jy2 - jy1) * (jx2 - jx1);
        for (int i = ib; i < ib + 64; ++i) {
            float cfi = (float)scl[i];
            float iy1 = sy1[i] + 2.0f * cfi;
            float ix1 = sx1[i] + 2.0f * cfi;
            float iy2 = sy2[i] + 2.0f * cfi;
            float ix2 = sx2[i] + 2.0f * cfi;
            float iar = (iy2 - iy1) * (ix2 - ix1);
            float yy1 = fmaxf(iy1, jy1);
            float xx1 = fmaxf(ix1, jx1);
            float yy2 = fminf(iy2, jy2);
            float xx2 = fminf(ix2, jx2);
            float inter = fmaxf(yy2 - yy1, 0.0f) * fmaxf(xx2 - xx1, 0.0f);
            float uni = iar + jar - inter;
            float iou = inter / fmaxf(uni, 1e-12f);
            unsigned bal = __ballot_sync(0xffffffffu, iou > 0.3f);
            if (lane == 0) Mm[i * 8 + wcol] = bal;
        }
    }
    __syncthreads();

    // warp-parallel greedy over 8 chunks of 32 candidates
    if (wrp == 0) {
        unsigned rem[8] = {0, 0, 0, 0, 0, 0, 0, 0};
        int kc = 0;
        bool done = false;
        unsigned lower = (1u << lane) - 1u;
        for (int c = 0; c < 8 && !done; ++c) {
            int i = c * 32 + lane;
            unsigned row[8];
#pragma unroll
            for (int w = 0; w < 8; ++w) row[w] = Mm[i * 8 + w];
            bool v = ssc[i] > 0.0f;
            bool psup = (rem[c] >> lane) & 1u;
            unsigned wchunk = row[c] & lower;  // same-chunk earlier (symmetry)

            bool k = v && !psup;
            unsigned km = __ballot_sync(0xffffffffu, k);
            for (int it = 0; it < 40; ++it) {
                bool kn = v && !psup && ((wchunk & km) == 0u);
                unsigned km2 = __ballot_sync(0xffffffffu, kn);
                if (km2 == km) break;
                km = km2;
            }
            k = (km >> lane) & 1u;

            if (km) {
                int cnt = __popc(km);
                int need = MAXI - kc;
                int pos = __popc(km & lower);
                if (k && pos < need) {
                    float* dr = det + (b * MAXI + kc + pos) * 6;
                    dr[0] = sy1[i]; dr[1] = sx1[i]; dr[2] = sy2[i]; dr[3] = sx2[i];
                    dr[4] = (float)scl[i]; dr[5] = ssc[i];
                }
                if (cnt >= need) {
                    kc = MAXI;
                    done = true;
                } else {
#pragma unroll
                    for (int w = 0; w < 8; ++w)
                        rem[w] |= __reduce_or_sync(0xffffffffu, k ? row[w] : 0u);
                    kc += cnt;
                }
            }
        }
        if (lane == 0) {
            s_kc = kc;
            s_fb = (kc < MAXI && (unsigned)(s[MSEL] >> 32) != 0u) ? 1 : 0;
        }
    }
    __syncthreads();

    // rare fallback: serial warp NMS from scratch over full sorted list
    if (s_fb && wrp == 0) {
        int kc = 0;
        for (int i = 0; i < NN && kc < MAXI; ++i) {
            unsigned long long key = s[i];
            unsigned sb = (unsigned)(key >> 32);
            if (!sb) break;
            int idx = (int)(0xFFFFFFFFu - (unsigned)(key & 0xFFFFFFFFull));
            int gi = b * NN + idx;
            float4 bx = g_box4[gi];
            float y1 = bx.x, x1 = bx.y, y2 = bx.z, x2 = bx.w;
            float cf = (float)g_cls[gi];
            float score = __uint_as_float(sb);
            float oy1 = y1 + 2.0f * cf, ox1 = x1 + 2.0f * cf;
            float oy2 = y2 + 2.0f * cf, ox2 = x2 + 2.0f * cf;
            float ar = (oy2 - oy1) * (ox2 - ox1);
            bool sup = false;
            for (int j = lane; j < kc; j += 32) {
                float yy1 = fmaxf(oy1, ky1[j]);
                float xx1 = fmaxf(ox1, kx1[j]);
                float yy2 = fminf(oy2, ky2[j]);
                float xx2 = fminf(ox2, kx2[j]);
                float inter = fmaxf(yy2 - yy1, 0.0f) * fmaxf(xx2 - xx1, 0.0f);
                float uni = ar + kar[j] - inter;
                float iou = inter / fmaxf(uni, 1e-12f);
                sup |= (iou > 0.3f);
            }
            if (!__any_sync(0xffffffffu, sup)) {
                if (lane == 0) {
                    ky1[kc] = oy1; kx1[kc] = ox1; ky2[kc] = oy2; kx2[kc] = ox2;
                    kar[kc] = ar;
                    float* dr = det + (b * MAXI + kc) * 6;
                    dr[0] = y1; dr[1] = x1; dr[2] = y2; dr[3] = x2;
                    dr[4] = cf; dr[5] = score;
                }
                kc++;
            }
            __syncwarp();
        }
        if (lane == 0) s_kc = kc;
    }
    __syncthreads();

    int kc = s_kc;
    for (int t = tid; t < (MAXI - kc) * 6; t += 1024)
        det[(b * MAXI + kc) * 6 + t] = 0.0f;
}

// ---------------------------------------------------------------------------
// K4: mask. Block = 8 rows of one batch, 1024 threads, 2 barriers total.
// Threads 0-799 compact intervals for (row=tid/100, box=tid%100); then
// (row=tid>>7, grp=tid&127) threads write one float4 each.
// ---------------------------------------------------------------------------
__global__ void __launch_bounds__(1024) k4_mask(const float* __restrict__ det,
                                                float* __restrict__ mask) {
    int b = blockIdx.y;
    int h0 = blockIdx.x * 8;
    int tid = threadIdx.x;
    __shared__ float ax1[8][MAXI], ax2[8][MAXI];
    __shared__ int nact[8];

    if (tid < 8) nact[tid] = 0;
    __syncthreads();

    if (tid < 8 * MAXI) {
        int r = tid / MAXI;
        int d = tid - r * MAXI;
        const float* dr = det + (b * MAXI + d) * 6;
        float2 a = *(const float2*)(dr);      // y1,x1
        float2 c = *(const float2*)(dr + 2);  // y2,x2
        float ys = ((float)(h0 + r) + 0.5f) * (1.0f / 512.0f);
        if (ys >= a.x && ys < c.x) {
            int p = atomicAdd(&nact[r], 1);
            ax1[r][p] = a.y;
            ax2[r][p] = c.y;
        }
    }
    __syncthreads();

    int r = tid >> 7;
    int g = tid & 127;
    int na = nact[r];
    float xb = (float)(g * 4);
    float xs0 = (xb + 0.5f) * (1.0f / 512.0f);
    float xs1 = (xb + 1.5f) * (1.0f / 512.0f);
    float xs2 = (xb + 2.5f) * (1.0f / 512.0f);
    float xs3 = (xb + 3.5f) * (1.0f / 512.0f);
    float4 o = make_float4(0.f, 0.f, 0.f, 0.f);
    for (int j = 0; j < na; ++j) {
        float a = ax1[r][j], c = ax2[r][j];
        if (xs0 >= a && xs0 < c) o.x = 1.0f;
        if (xs1 >= a && xs1 < c) o.y = 1.0f;
        if (xs2 >= a && xs2 < c) o.z = 1.0f;
        if (xs3 >= a && xs3 < c) o.w = 1.0f;
    }
    ((float4*)(mask + ((long long)(b * HH + h0 + r)) * WW))[g] = o;
}

// ---------------------------------------------------------------------------
extern "C" void kernel_launch(void* const* d_in, const int* in_sizes, int n_in,
                              void* d_out, int out_size) {
    const float* rois = (const float*)d_in[0];
    const float* probs = (const float*)d_in[1];
    const float* deltas = (const float*)d_in[2];
    const float* stdv = (const float*)d_in[3];
    float* det = (float*)d_out;                   // [B,100,6]
    float* mask = (float*)d_out + BB * MAXI * 6;  // [B,512,512]

    // 4 proposals per warp -> 4000 warps
    k1_refine<<<(4000 * 32 + 255) / 256, 256>>>(rois, probs, deltas, stdv);
    k23_sortnms<<<BB, 1024>>>(det);
    dim3 grid(HH / 8, BB);
    k4_mask<<<grid, 1024>>>(det, mask);
}